// round 5
// baseline (speedup 1.0000x reference)
#include <cuda_runtime.h>

#define BB   4
#define TQ   256
#define TV   2048
#define DD   512
#define UU   128
#define NROWS_Q (BB*TQ)          // 1024
#define NROWS_K (BB*TV)          // 8192
#define CTX_SIZE (NROWS_Q*UU)    // 131072
#define WTS_SIZE (NROWS_Q*TV)    // 2097152

// Scratch (no cudaMalloc allowed)
__device__ float g_q[NROWS_Q*UU];        // 0.5 MB
__device__ float g_k[NROWS_K*UU];        // 4 MB
__device__ float g_scores[NROWS_Q*TV];   // 8 MB
__device__ float g_part[4][CTX_SIZE];    // 2 MB

__device__ __forceinline__ float ex2f_(float x){ float y; asm("ex2.approx.f32 %0, %1;" : "=f"(y) : "f"(x)); return y; }
__device__ __forceinline__ float rcpf_(float x){ float y; asm("rcp.approx.f32 %0, %1;" : "=f"(y) : "f"(x)); return y; }

// ---------------------------------------------------------------------------
// Kernel 1: projections. C[M,128] = A[M,512] @ W[512,128], fp32.
// bid<16 -> q (M=1024), else -> k (M=8192). BM=64, BN=128, BK=16, tile 4x8.
// ---------------------------------------------------------------------------
__global__ __launch_bounds__(256) void proj_gemm(
    const float* __restrict__ dq, const float* __restrict__ ev,
    const float* __restrict__ W1, const float* __restrict__ W2)
{
    __shared__ float As[16][68];    // [kk][m], padded
    __shared__ float Bs[16][128];   // [kk][n]

    int bid = blockIdx.x;
    const float* A; const float* W; float* C; int mbase;
    if (bid < 16) { A = dq; W = W1; C = g_q; mbase = bid * 64; }
    else          { A = ev; W = W2; C = g_k; mbase = (bid - 16) * 64; }

    int t  = threadIdx.x;
    int ty = t >> 4;          // 0..15 (row group)
    int tx = t & 15;          // 0..15 (col group)
    int lr = t >> 2;          // 0..63 (A load row)
    int lc = (t & 3) << 2;    // 0,4,8,12 (A load col quad)

    float acc[4][8];
    #pragma unroll
    for (int i = 0; i < 4; i++)
        #pragma unroll
        for (int j = 0; j < 8; j++) acc[i][j] = 0.0f;

    for (int k0 = 0; k0 < DD; k0 += 16) {
        float4 av = *(const float4*)&A[(size_t)(mbase + lr) * DD + k0 + lc];
        As[lc + 0][lr] = av.x; As[lc + 1][lr] = av.y;
        As[lc + 2][lr] = av.z; As[lc + 3][lr] = av.w;
        {
            int i0 = t, i1 = t + 256;
            *(float4*)&Bs[i0 >> 5][(i0 & 31) << 2] =
                *(const float4*)&W[(size_t)(k0 + (i0 >> 5)) * UU + ((i0 & 31) << 2)];
            *(float4*)&Bs[i1 >> 5][(i1 & 31) << 2] =
                *(const float4*)&W[(size_t)(k0 + (i1 >> 5)) * UU + ((i1 & 31) << 2)];
        }
        __syncthreads();

        #pragma unroll
        for (int kk = 0; kk < 16; kk++) {
            float4 a4 = *(const float4*)&As[kk][ty * 4];
            float4 b0 = *(const float4*)&Bs[kk][tx * 4];
            float4 b1 = *(const float4*)&Bs[kk][64 + tx * 4];
            float a[4] = {a4.x, a4.y, a4.z, a4.w};
            float b[8] = {b0.x, b0.y, b0.z, b0.w, b1.x, b1.y, b1.z, b1.w};
            #pragma unroll
            for (int i = 0; i < 4; i++)
                #pragma unroll
                for (int j = 0; j < 8; j++)
                    acc[i][j] = fmaf(a[i], b[j], acc[i][j]);
        }
        __syncthreads();
    }

    #pragma unroll
    for (int i = 0; i < 4; i++) {
        int row = mbase + ty * 4 + i;
        *(float4*)&C[(size_t)row * UU + tx * 4] =
            make_float4(acc[i][0], acc[i][1], acc[i][2], acc[i][3]);
        *(float4*)&C[(size_t)row * UU + 64 + tx * 4] =
            make_float4(acc[i][4], acc[i][5], acc[i][6], acc[i][7]);
    }
}

// ---------------------------------------------------------------------------
// Kernel 2: scores[b,q,v] = sum_u scale[u] * tanh(q[b,q,u] + k[b,v,u])
// Block tile: 16 q x 64 v, full U=128 in smem. Thread: 4 q x 1 v.
// tanh(x) = 1 - 2/(exp(2x)+1) via ex2.approx + rcp.approx (rel err ~1e-6).
// ---------------------------------------------------------------------------
__global__ __launch_bounds__(256) void scores_kernel(const float* __restrict__ scale)
{
    __shared__ __align__(16) float Qs[16][136];  // 136-float stride: 16B-aligned rows, <=2-way LDS conflicts
    __shared__ __align__(16) float Ks[64][136];
    __shared__ __align__(16) float Ss[128];

    int b  = blockIdx.z;
    int qt = blockIdx.y;
    int vt = blockIdx.x;
    int t  = threadIdx.x;

    const float* qg = g_q + (size_t)(b * TQ + qt * 16) * UU;
    const float* kg = g_k + (size_t)(b * TV + vt * 64) * UU;

    #pragma unroll
    for (int j = 0; j < 2; j++) {
        int i = t + j * 256;
        int r = i >> 5, c = (i & 31) << 2;
        *(float4*)&Qs[r][c] = *(const float4*)&qg[(size_t)r * UU + c];
    }
    #pragma unroll
    for (int j = 0; j < 8; j++) {
        int i = t + j * 256;
        int r = i >> 5, c = (i & 31) << 2;
        *(float4*)&Ks[r][c] = *(const float4*)&kg[(size_t)r * UU + c];
    }
    if (t < 32) *(float4*)&Ss[t * 4] = *(const float4*)&scale[t * 4];
    __syncthreads();

    int v   = t & 63;    // consecutive lanes -> consecutive K rows
    int qg4 = t >> 6;    // 0..3 -> q rows qg4*4 .. +3

    const float4* K4 = (const float4*)&Ks[v][0];
    const float4* S4 = (const float4*)&Ss[0];

    float acc[4] = {0.0f, 0.0f, 0.0f, 0.0f};
    const float C2 = 2.88539008177792681f;   // 2*log2(e)

    #pragma unroll 8
    for (int uc = 0; uc < 32; uc++) {
        float4 kv = K4[uc];
        float4 sv = S4[uc];
        #pragma unroll
        for (int i = 0; i < 4; i++) {
            float4 qv = *(const float4*)&Qs[qg4 * 4 + i][uc * 4];
            float s = acc[i];
            { float x = qv.x + kv.x; float e = ex2f_(x * C2); float r = rcpf_(e + 1.0f);
              s = fmaf(sv.x, fmaf(-2.0f, r, 1.0f), s); }
            { float x = qv.y + kv.y; float e = ex2f_(x * C2); float r = rcpf_(e + 1.0f);
              s = fmaf(sv.y, fmaf(-2.0f, r, 1.0f), s); }
            { float x = qv.z + kv.z; float e = ex2f_(x * C2); float r = rcpf_(e + 1.0f);
              s = fmaf(sv.z, fmaf(-2.0f, r, 1.0f), s); }
            { float x = qv.w + kv.w; float e = ex2f_(x * C2); float r = rcpf_(e + 1.0f);
              s = fmaf(sv.w, fmaf(-2.0f, r, 1.0f), s); }
            acc[i] = s;
        }
    }

    float* out = g_scores + (size_t)(b * TQ + qt * 16 + qg4 * 4) * TV + vt * 64 + v;
    out[0]      = acc[0];
    out[TV]     = acc[1];
    out[2 * TV] = acc[2];
    out[3 * TV] = acc[3];
}

// ---------------------------------------------------------------------------
// Kernel 3: row softmax over Tv=2048. One block per (b,q) row.
// Writes weights into d_out (after the context region).
// ---------------------------------------------------------------------------
__global__ __launch_bounds__(256) void softmax_kernel(float* __restrict__ wout)
{
    __shared__ float red[8];
    int row = blockIdx.x;
    int t   = threadIdx.x;

    const float4* in4 = (const float4*)(g_scores + (size_t)row * TV);
    float4 a = in4[t];
    float4 b = in4[t + 256];

    float m = fmaxf(fmaxf(fmaxf(a.x, a.y), fmaxf(a.z, a.w)),
                    fmaxf(fmaxf(b.x, b.y), fmaxf(b.z, b.w)));
    #pragma unroll
    for (int off = 16; off; off >>= 1)
        m = fmaxf(m, __shfl_xor_sync(0xffffffffu, m, off));
    if ((t & 31) == 0) red[t >> 5] = m;
    __syncthreads();
    m = red[0];
    #pragma unroll
    for (int i = 1; i < 8; i++) m = fmaxf(m, red[i]);

    const float L2E = 1.44269504088896341f;
    float e0 = ex2f_((a.x - m) * L2E), e1 = ex2f_((a.y - m) * L2E);
    float e2 = ex2f_((a.z - m) * L2E), e3 = ex2f_((a.w - m) * L2E);
    float e4 = ex2f_((b.x - m) * L2E), e5 = ex2f_((b.y - m) * L2E);
    float e6 = ex2f_((b.z - m) * L2E), e7 = ex2f_((b.w - m) * L2E);
    float s = ((e0 + e1) + (e2 + e3)) + ((e4 + e5) + (e6 + e7));
    #pragma unroll
    for (int off = 16; off; off >>= 1)
        s += __shfl_xor_sync(0xffffffffu, s, off);
    __syncthreads();                       // red reads above done
    if ((t & 31) == 0) red[t >> 5] = s;
    __syncthreads();
    float tot = 0.0f;
    #pragma unroll
    for (int i = 0; i < 8; i++) tot += red[i];
    float inv = rcpf_(tot);

    float4* o4 = (float4*)(wout + (size_t)row * TV);
    o4[t]       = make_float4(e0 * inv, e1 * inv, e2 * inv, e3 * inv);
    o4[t + 256] = make_float4(e4 * inv, e5 * inv, e6 * inv, e7 * inv);
}

// ---------------------------------------------------------------------------
// Kernel 4: context partials. ctx[b,q,u] = sum_v w[b,q,v]*k[b,v,u].
// Grid (4 v-chunks, 64 row-tiles of 16). 128 threads = one per u.
// ---------------------------------------------------------------------------
__global__ __launch_bounds__(128) void ctx_partial(const float* __restrict__ wts)
{
    __shared__ float Ks2[64][128];
    __shared__ float Wst[64][20];   // [v][q], padded stride 20 (16B-aligned rows)

    int chunk = blockIdx.x;          // 0..3 -> v in [chunk*512, +512)
    int rt    = blockIdx.y;          // 0..63
    int r0    = rt * 16;             // global row base (b*256+q)
    int bbb   = r0 >> 8;             // batch
    int t     = threadIdx.x;         // u

    float acc[16];
    #pragma unroll
    for (int q = 0; q < 16; q++) acc[q] = 0.0f;

    for (int vt = 0; vt < 8; vt++) {
        int vbase = chunk * 512 + vt * 64;
        #pragma unroll
        for (int j = 0; j < 16; j++) {
            int i = t + j * 128;
            int v = i >> 5, c = (i & 31) << 2;
            *(float4*)&Ks2[v][c] =
                *(const float4*)&g_k[(size_t)(bbb * TV + vbase + v) * UU + c];
        }
        #pragma unroll
        for (int j = 0; j < 8; j++) {
            int i = t + j * 128;
            int q = i >> 6, v = i & 63;
            Wst[v][q] = wts[(size_t)(r0 + q) * TV + vbase + v];
        }
        __syncthreads();

        #pragma unroll 4
        for (int v = 0; v < 64; v++) {
            float kv  = Ks2[v][t];
            float4 w0 = *(const float4*)&Wst[v][0];
            float4 w1 = *(const float4*)&Wst[v][4];
            float4 w2 = *(const float4*)&Wst[v][8];
            float4 w3 = *(const float4*)&Wst[v][12];
            acc[0]  = fmaf(w0.x, kv, acc[0]);  acc[1]  = fmaf(w0.y, kv, acc[1]);
            acc[2]  = fmaf(w0.z, kv, acc[2]);  acc[3]  = fmaf(w0.w, kv, acc[3]);
            acc[4]  = fmaf(w1.x, kv, acc[4]);  acc[5]  = fmaf(w1.y, kv, acc[5]);
            acc[6]  = fmaf(w1.z, kv, acc[6]);  acc[7]  = fmaf(w1.w, kv, acc[7]);
            acc[8]  = fmaf(w2.x, kv, acc[8]);  acc[9]  = fmaf(w2.y, kv, acc[9]);
            acc[10] = fmaf(w2.z, kv, acc[10]); acc[11] = fmaf(w2.w, kv, acc[11]);
            acc[12] = fmaf(w3.x, kv, acc[12]); acc[13] = fmaf(w3.y, kv, acc[13]);
            acc[14] = fmaf(w3.z, kv, acc[14]); acc[15] = fmaf(w3.w, kv, acc[15]);
        }
        __syncthreads();
    }

    #pragma unroll
    for (int q = 0; q < 16; q++)
        g_part[chunk][(size_t)(r0 + q) * UU + t] = acc[q];
}

// ---------------------------------------------------------------------------
// Kernel 5: reduce 4 partials -> context into d_out[0 .. CTX_SIZE)
// ---------------------------------------------------------------------------
__global__ __launch_bounds__(256) void ctx_reduce(float* __restrict__ out)
{
    int i = blockIdx.x * 256 + threadIdx.x;   // float4 index, 32768 total
    const float4* p0 = (const float4*)g_part[0];
    const float4* p1 = (const float4*)g_part[1];
    const float4* p2 = (const float4*)g_part[2];
    const float4* p3 = (const float4*)g_part[3];
    float4 a = p0[i], b = p1[i], c = p2[i], d = p3[i];
    ((float4*)out)[i] = make_float4(a.x + b.x + c.x + d.x,
                                    a.y + b.y + c.y + d.y,
                                    a.z + b.z + c.z + d.z,
                                    a.w + b.w + c.w + d.w);
}

extern "C" void kernel_launch(void* const* d_in, const int* in_sizes, int n_in,
                              void* d_out, int out_size)
{
    (void)in_sizes; (void)n_in; (void)out_size;
    const float* dq    = (const float*)d_in[0];   // [4,256,512]
    const float* ev    = (const float*)d_in[1];   // [4,2048,512]
    const float* W1    = (const float*)d_in[2];   // [512,128]
    const float* W2    = (const float*)d_in[3];   // [512,128]
    const float* scale = (const float*)d_in[4];   // [128]
    float* out = (float*)d_out;                   // context [131072] ++ weights [2097152]
    float* wout = out + CTX_SIZE;

    proj_gemm<<<144, 256>>>(dq, ev, W1, W2);
    scores_kernel<<<dim3(TV / 64, TQ / 16, BB), 256>>>(scale);
    softmax_kernel<<<NROWS_Q, 256>>>(wout);
    ctx_partial<<<dim3(4, 64), 128>>>(wout);
    ctx_reduce<<<CTX_SIZE / 4 / 256, 256>>>(out);
}

// round 7
// speedup vs baseline: 1.3127x; 1.3127x over previous
#include <cuda_runtime.h>

#define BB   4
#define TQ   256
#define TV   2048
#define DD   512
#define UU   128
#define NROWS_Q (BB*TQ)          // 1024
#define NROWS_K (BB*TV)          // 8192
#define CTX_SIZE (NROWS_Q*UU)    // 131072
#define NCHUNK 8

// Scratch (no cudaMalloc allowed)
__device__ float g_eq[NROWS_Q*UU];          // e^{2q}  0.5 MB
__device__ float g_k [NROWS_K*UU];          // raw k   4 MB
__device__ float g_ek[NROWS_K*UU];          // e^{2k}  4 MB
__device__ float g_scores[NROWS_Q*TV];      // 8 MB
__device__ float g_part[NCHUNK][CTX_SIZE];  // 4 MB

__device__ __forceinline__ float ex2f_(float x){ float y; asm("ex2.approx.f32 %0, %1;" : "=f"(y) : "f"(x)); return y; }
__device__ __forceinline__ float rcpf_(float x){ float y; asm("rcp.approx.f32 %0, %1;" : "=f"(y) : "f"(x)); return y; }

#define C2E 2.88539008177792681f   /* 2*log2(e) */

// ---------------------------------------------------------------------------
// Kernel 1: projections + exp epilogue.
// C[M,128] = A[M,512] @ W[512,128] fp32. bid<16 -> q (store e^{2q} only),
// else -> k (store raw k AND e^{2k}). BM=64, BN=128, BK=16, thread tile 4x8.
// ---------------------------------------------------------------------------
__global__ __launch_bounds__(256) void proj_gemm(
    const float* __restrict__ dq, const float* __restrict__ ev,
    const float* __restrict__ W1, const float* __restrict__ W2)
{
    __shared__ float As[16][68];    // [kk][m], padded
    __shared__ float Bs[16][128];   // [kk][n]

    int bid = blockIdx.x;
    bool isq = (bid < 16);
    const float* A; const float* W; int mbase;
    if (isq) { A = dq; W = W1; mbase = bid * 64; }
    else     { A = ev; W = W2; mbase = (bid - 16) * 64; }

    int t  = threadIdx.x;
    int ty = t >> 4;          // 0..15 (row group)
    int tx = t & 15;          // 0..15 (col group)
    int lr = t >> 2;          // 0..63 (A load row)
    int lc = (t & 3) << 2;    // 0,4,8,12 (A load col quad)

    float acc[4][8];
    #pragma unroll
    for (int i = 0; i < 4; i++)
        #pragma unroll
        for (int j = 0; j < 8; j++) acc[i][j] = 0.0f;

    for (int k0 = 0; k0 < DD; k0 += 16) {
        float4 av = *(const float4*)&A[(size_t)(mbase + lr) * DD + k0 + lc];
        As[lc + 0][lr] = av.x; As[lc + 1][lr] = av.y;
        As[lc + 2][lr] = av.z; As[lc + 3][lr] = av.w;
        {
            int i0 = t, i1 = t + 256;
            *(float4*)&Bs[i0 >> 5][(i0 & 31) << 2] =
                *(const float4*)&W[(size_t)(k0 + (i0 >> 5)) * UU + ((i0 & 31) << 2)];
            *(float4*)&Bs[i1 >> 5][(i1 & 31) << 2] =
                *(const float4*)&W[(size_t)(k0 + (i1 >> 5)) * UU + ((i1 & 31) << 2)];
        }
        __syncthreads();

        #pragma unroll
        for (int kk = 0; kk < 16; kk++) {
            float4 a4 = *(const float4*)&As[kk][ty * 4];
            float4 b0 = *(const float4*)&Bs[kk][tx * 4];
            float4 b1 = *(const float4*)&Bs[kk][64 + tx * 4];
            float a[4] = {a4.x, a4.y, a4.z, a4.w};
            float b[8] = {b0.x, b0.y, b0.z, b0.w, b1.x, b1.y, b1.z, b1.w};
            #pragma unroll
            for (int i = 0; i < 4; i++)
                #pragma unroll
                for (int j = 0; j < 8; j++)
                    acc[i][j] = fmaf(a[i], b[j], acc[i][j]);
        }
        __syncthreads();
    }

    #pragma unroll
    for (int i = 0; i < 4; i++) {
        int row = mbase + ty * 4 + i;
        size_t o0 = (size_t)row * UU + tx * 4;
        size_t o1 = o0 + 64;
        float4 e0 = make_float4(ex2f_(acc[i][0]*C2E), ex2f_(acc[i][1]*C2E),
                                ex2f_(acc[i][2]*C2E), ex2f_(acc[i][3]*C2E));
        float4 e1 = make_float4(ex2f_(acc[i][4]*C2E), ex2f_(acc[i][5]*C2E),
                                ex2f_(acc[i][6]*C2E), ex2f_(acc[i][7]*C2E));
        if (isq) {
            *(float4*)&g_eq[o0] = e0;
            *(float4*)&g_eq[o1] = e1;
        } else {
            *(float4*)&g_k[o0] = make_float4(acc[i][0], acc[i][1], acc[i][2], acc[i][3]);
            *(float4*)&g_k[o1] = make_float4(acc[i][4], acc[i][5], acc[i][6], acc[i][7]);
            *(float4*)&g_ek[o0] = e0;
            *(float4*)&g_ek[o1] = e1;
        }
    }
}

// ---------------------------------------------------------------------------
// Kernel 2: scores via factorized exp.
// tanh(q+k) = 1 - 2/(1 + Eq*Ek).  score' = -2 * sum_u scale_u / (1+Eq*Ek)
// (constant Sum(scale) shift dropped — softmax is shift-invariant; scores
//  are not an output, only weights/context are).
// Block tile: 16 q x 64 v, full U=128. Thread: 4 q x 1 v. 1 MUFU + 2 FMA/elem.
// ---------------------------------------------------------------------------
__global__ __launch_bounds__(256) void scores_kernel(const float* __restrict__ scale)
{
    __shared__ __align__(16) float Qs[16][136];
    __shared__ __align__(16) float Ks[64][136];
    __shared__ __align__(16) float Ss[128];

    int b  = blockIdx.z;
    int qt = blockIdx.y;
    int vt = blockIdx.x;
    int t  = threadIdx.x;

    const float* qg = g_eq + (size_t)(b * TQ + qt * 16) * UU;
    const float* kg = g_ek + (size_t)(b * TV + vt * 64) * UU;

    #pragma unroll
    for (int j = 0; j < 2; j++) {
        int i = t + j * 256;
        int r = i >> 5, c = (i & 31) << 2;
        *(float4*)&Qs[r][c] = *(const float4*)&qg[(size_t)r * UU + c];
    }
    #pragma unroll
    for (int j = 0; j < 8; j++) {
        int i = t + j * 256;
        int r = i >> 5, c = (i & 31) << 2;
        *(float4*)&Ks[r][c] = *(const float4*)&kg[(size_t)r * UU + c];
    }
    if (t < 32) *(float4*)&Ss[t * 4] = *(const float4*)&scale[t * 4];
    __syncthreads();

    int v   = t & 63;
    int qg4 = t >> 6;

    const float4* K4 = (const float4*)&Ks[v][0];
    const float4* S4 = (const float4*)&Ss[0];

    float acc[4] = {0.0f, 0.0f, 0.0f, 0.0f};

    #pragma unroll 8
    for (int uc = 0; uc < 32; uc++) {
        float4 kv = K4[uc];
        float4 sv = S4[uc];
        #pragma unroll
        for (int i = 0; i < 4; i++) {
            float4 qv = *(const float4*)&Qs[qg4 * 4 + i][uc * 4];
            float s = acc[i];
            { float p = fmaf(qv.x, kv.x, 1.0f); float r = rcpf_(p); s = fmaf(sv.x, r, s); }
            { float p = fmaf(qv.y, kv.y, 1.0f); float r = rcpf_(p); s = fmaf(sv.y, r, s); }
            { float p = fmaf(qv.z, kv.z, 1.0f); float r = rcpf_(p); s = fmaf(sv.z, r, s); }
            { float p = fmaf(qv.w, kv.w, 1.0f); float r = rcpf_(p); s = fmaf(sv.w, r, s); }
            acc[i] = s;
        }
    }

    float* out = g_scores + (size_t)(b * TQ + qt * 16 + qg4 * 4) * TV + vt * 64 + v;
    out[0]      = -2.0f * acc[0];
    out[TV]     = -2.0f * acc[1];
    out[2 * TV] = -2.0f * acc[2];
    out[3 * TV] = -2.0f * acc[3];
}

// ---------------------------------------------------------------------------
// Kernel 3: row softmax over Tv=2048. One block per (b,q) row.
// ---------------------------------------------------------------------------
__global__ __launch_bounds__(256) void softmax_kernel(float* __restrict__ wout)
{
    __shared__ float red[8];
    int row = blockIdx.x;
    int t   = threadIdx.x;

    const float4* in4 = (const float4*)(g_scores + (size_t)row * TV);
    float4 a = in4[t];
    float4 b = in4[t + 256];

    float m = fmaxf(fmaxf(fmaxf(a.x, a.y), fmaxf(a.z, a.w)),
                    fmaxf(fmaxf(b.x, b.y), fmaxf(b.z, b.w)));
    #pragma unroll
    for (int off = 16; off; off >>= 1)
        m = fmaxf(m, __shfl_xor_sync(0xffffffffu, m, off));
    if ((t & 31) == 0) red[t >> 5] = m;
    __syncthreads();
    m = red[0];
    #pragma unroll
    for (int i = 1; i < 8; i++) m = fmaxf(m, red[i]);

    const float L2E = 1.44269504088896341f;
    float e0 = ex2f_((a.x - m) * L2E), e1 = ex2f_((a.y - m) * L2E);
    float e2 = ex2f_((a.z - m) * L2E), e3 = ex2f_((a.w - m) * L2E);
    float e4 = ex2f_((b.x - m) * L2E), e5 = ex2f_((b.y - m) * L2E);
    float e6 = ex2f_((b.z - m) * L2E), e7 = ex2f_((b.w - m) * L2E);
    float s = ((e0 + e1) + (e2 + e3)) + ((e4 + e5) + (e6 + e7));
    #pragma unroll
    for (int off = 16; off; off >>= 1)
        s += __shfl_xor_sync(0xffffffffu, s, off);
    __syncthreads();
    if ((t & 31) == 0) red[t >> 5] = s;
    __syncthreads();
    float tot = 0.0f;
    #pragma unroll
    for (int i = 0; i < 8; i++) tot += red[i];
    float inv = rcpf_(tot);

    float4* o4 = (float4*)(wout + (size_t)row * TV);
    o4[t]       = make_float4(e0 * inv, e1 * inv, e2 * inv, e3 * inv);
    o4[t + 256] = make_float4(e4 * inv, e5 * inv, e6 * inv, e7 * inv);
}

// ---------------------------------------------------------------------------
// Kernel 4: context partials. ctx[b,q,u] = sum_v w[b,q,v]*k[b,v,u].
// Grid (8 v-chunks of 256, 64 row-tiles of 16 q). 256 threads:
// thread = (u = t&127, qh = t>>7 owning 8 q rows). 512 blocks x 8 warps.
// ---------------------------------------------------------------------------
__global__ __launch_bounds__(256) void ctx_partial(const float* __restrict__ wts)
{
    __shared__ float Ks2[64][128];
    __shared__ float Wst[64][20];   // [v][q], stride 20 (16B-aligned rows)

    int chunk = blockIdx.x;          // 0..7 -> v in [chunk*256, +256)
    int rt    = blockIdx.y;          // 0..63
    int r0    = rt * 16;             // global row base (b*256+q)
    int bbb   = r0 >> 8;             // batch
    int t     = threadIdx.x;
    int u     = t & 127;
    int qh    = t >> 7;              // 0..1 -> q rows qh*8 .. qh*8+7

    float acc[8];
    #pragma unroll
    for (int q = 0; q < 8; q++) acc[q] = 0.0f;

    #pragma unroll 1
    for (int vt = 0; vt < 4; vt++) {
        int vbase = chunk * 256 + vt * 64;
        #pragma unroll
        for (int j = 0; j < 8; j++) {
            int i = t + j * 256;
            int v = i >> 5, c = (i & 31) << 2;
            *(float4*)&Ks2[v][c] =
                *(const float4*)&g_k[(size_t)(bbb * TV + vbase + v) * UU + c];
        }
        #pragma unroll
        for (int j = 0; j < 4; j++) {
            int i = t + j * 256;
            int q = i >> 6, v = i & 63;
            Wst[v][q] = wts[(size_t)(r0 + q) * TV + vbase + v];
        }
        __syncthreads();

        #pragma unroll 8
        for (int v = 0; v < 64; v++) {
            float kv  = Ks2[v][u];
            float4 w0 = *(const float4*)&Wst[v][qh * 8];
            float4 w1 = *(const float4*)&Wst[v][qh * 8 + 4];
            acc[0] = fmaf(w0.x, kv, acc[0]);  acc[1] = fmaf(w0.y, kv, acc[1]);
            acc[2] = fmaf(w0.z, kv, acc[2]);  acc[3] = fmaf(w0.w, kv, acc[3]);
            acc[4] = fmaf(w1.x, kv, acc[4]);  acc[5] = fmaf(w1.y, kv, acc[5]);
            acc[6] = fmaf(w1.z, kv, acc[6]);  acc[7] = fmaf(w1.w, kv, acc[7]);
        }
        __syncthreads();
    }

    #pragma unroll
    for (int q = 0; q < 8; q++)
        g_part[chunk][(size_t)(r0 + qh * 8 + q) * UU + u] = acc[q];
}

// ---------------------------------------------------------------------------
// Kernel 5: reduce 8 partials -> context into d_out[0 .. CTX_SIZE)
// ---------------------------------------------------------------------------
__global__ __launch_bounds__(256) void ctx_reduce(float* __restrict__ out)
{
    int i = blockIdx.x * 256 + threadIdx.x;   // float4 index, 32768 total
    float4 s = ((const float4*)g_part[0])[i];
    #pragma unroll
    for (int c = 1; c < NCHUNK; c++) {
        float4 p = ((const float4*)g_part[c])[i];
        s.x += p.x; s.y += p.y; s.z += p.z; s.w += p.w;
    }
    ((float4*)out)[i] = s;
}

extern "C" void kernel_launch(void* const* d_in, const int* in_sizes, int n_in,
                              void* d_out, int out_size)
{
    (void)in_sizes; (void)n_in; (void)out_size;
    const float* dq    = (const float*)d_in[0];   // [4,256,512]
    const float* ev    = (const float*)d_in[1];   // [4,2048,512]
    const float* W1    = (const float*)d_in[2];   // [512,128]
    const float* W2    = (const float*)d_in[3];   // [512,128]
    const float* scale = (const float*)d_in[4];   // [128]
    float* out  = (float*)d_out;                  // context [131072] ++ weights [2097152]
    float* wout = out + CTX_SIZE;

    proj_gemm<<<144, 256>>>(dq, ev, W1, W2);
    scores_kernel<<<dim3(TV / 64, TQ / 16, BB), 256>>>(scale);
    softmax_kernel<<<NROWS_Q, 256>>>(wout);
    ctx_partial<<<dim3(NCHUNK, 64), 256>>>(wout);
    ctx_reduce<<<CTX_SIZE / 4 / 256, 256>>>(out);
}

// round 8
// speedup vs baseline: 1.4791x; 1.1268x over previous
#include <cuda_runtime.h>

#define BB   4
#define TQ   256
#define TV   2048
#define DD   512
#define UU   128
#define NROWS_Q (BB*TQ)          // 1024
#define NROWS_K (BB*TV)          // 8192
#define CTX_SIZE (NROWS_Q*UU)    // 131072
#define NCHUNK 8

typedef unsigned long long ull;

// Scratch (no cudaMalloc allowed)
__device__ float g_eq[NROWS_Q*UU];          // e^{2q}  0.5 MB
__device__ float g_k [NROWS_K*UU];          // raw k   4 MB
__device__ float g_ek[NROWS_K*UU];          // e^{2k}  4 MB
__device__ float g_scores[NROWS_Q*TV];      // 8 MB
__device__ float g_part[NCHUNK][CTX_SIZE];  // 4 MB

__device__ __forceinline__ float ex2f_(float x){ float y; asm("ex2.approx.f32 %0, %1;" : "=f"(y) : "f"(x)); return y; }
__device__ __forceinline__ float rcpf_(float x){ float y; asm("rcp.approx.f32 %0, %1;" : "=f"(y) : "f"(x)); return y; }

// Packed f32x2 (Blackwell): 2x fp32 FMA throughput, only reachable via PTX.
__device__ __forceinline__ ull pk2_(float lo, float hi){ ull r; asm("mov.b64 %0, {%1, %2};" : "=l"(r) : "f"(lo), "f"(hi)); return r; }
__device__ __forceinline__ void upk2_(ull v, float& lo, float& hi){ asm("mov.b64 {%0, %1}, %2;" : "=f"(lo), "=f"(hi) : "l"(v)); }
__device__ __forceinline__ ull fma2_(ull a, ull b, ull c){ ull d; asm("fma.rn.f32x2 %0, %1, %2, %3;" : "=l"(d) : "l"(a), "l"(b), "l"(c)); return d; }
__device__ __forceinline__ ull mul2_(ull a, ull b){ ull d; asm("mul.rn.f32x2 %0, %1, %2;" : "=l"(d) : "l"(a), "l"(b)); return d; }
__device__ __forceinline__ ull add2_(ull a, ull b){ ull d; asm("add.rn.f32x2 %0, %1, %2;" : "=l"(d) : "l"(a), "l"(b)); return d; }
#define ONE2 0x3F8000003F800000ULL

#define C2E 2.88539008177792681f   /* 2*log2(e) */

// ---------------------------------------------------------------------------
// Kernel 1: projections + exp epilogue, packed-FMA mainloop.
// C[M,128] = A[M,512] @ W[512,128] fp32. bid<16 -> q (store e^{2q} only),
// else -> k (store raw k AND e^{2k}). BM=64, BN=128, BK=16, thread 4m x (4 n-pairs).
// ---------------------------------------------------------------------------
__global__ __launch_bounds__(256) void proj_gemm(
    const float* __restrict__ dq, const float* __restrict__ ev,
    const float* __restrict__ W1, const float* __restrict__ W2)
{
    __shared__ __align__(16) float As[16][68];    // [kk][m], padded
    __shared__ __align__(16) float Bs[16][128];   // [kk][n]

    int bid = blockIdx.x;
    bool isq = (bid < 16);
    const float* A; const float* W; int mbase;
    if (isq) { A = dq; W = W1; mbase = bid * 64; }
    else     { A = ev; W = W2; mbase = (bid - 16) * 64; }

    int t  = threadIdx.x;
    int ty = t >> 4;          // 0..15 (row group)
    int tx = t & 15;          // 0..15 (col group)
    int lr = t >> 2;          // 0..63 (A load row)
    int lc = (t & 3) << 2;    // 0,4,8,12 (A load col quad)

    ull acc[4][4];
    #pragma unroll
    for (int i = 0; i < 4; i++)
        #pragma unroll
        for (int j = 0; j < 4; j++) acc[i][j] = 0ULL;

    for (int k0 = 0; k0 < DD; k0 += 16) {
        float4 av = *(const float4*)&A[(size_t)(mbase + lr) * DD + k0 + lc];
        As[lc + 0][lr] = av.x; As[lc + 1][lr] = av.y;
        As[lc + 2][lr] = av.z; As[lc + 3][lr] = av.w;
        {
            int i0 = t, i1 = t + 256;
            *(float4*)&Bs[i0 >> 5][(i0 & 31) << 2] =
                *(const float4*)&W[(size_t)(k0 + (i0 >> 5)) * UU + ((i0 & 31) << 2)];
            *(float4*)&Bs[i1 >> 5][(i1 & 31) << 2] =
                *(const float4*)&W[(size_t)(k0 + (i1 >> 5)) * UU + ((i1 & 31) << 2)];
        }
        __syncthreads();

        #pragma unroll
        for (int kk = 0; kk < 16; kk++) {
            float4 a4 = *(const float4*)&As[kk][ty * 4];
            ulonglong2 b0 = *(const ulonglong2*)&Bs[kk][tx * 4];
            ulonglong2 b1 = *(const ulonglong2*)&Bs[kk][64 + tx * 4];
            float a[4] = {a4.x, a4.y, a4.z, a4.w};
            #pragma unroll
            for (int i = 0; i < 4; i++) {
                ull ad = pk2_(a[i], a[i]);
                acc[i][0] = fma2_(ad, b0.x, acc[i][0]);
                acc[i][1] = fma2_(ad, b0.y, acc[i][1]);
                acc[i][2] = fma2_(ad, b1.x, acc[i][2]);
                acc[i][3] = fma2_(ad, b1.y, acc[i][3]);
            }
        }
        __syncthreads();
    }

    #pragma unroll
    for (int i = 0; i < 4; i++) {
        float c[8];
        upk2_(acc[i][0], c[0], c[1]); upk2_(acc[i][1], c[2], c[3]);
        upk2_(acc[i][2], c[4], c[5]); upk2_(acc[i][3], c[6], c[7]);
        int row = mbase + ty * 4 + i;
        size_t o0 = (size_t)row * UU + tx * 4;
        size_t o1 = o0 + 64;
        float4 e0 = make_float4(ex2f_(c[0]*C2E), ex2f_(c[1]*C2E),
                                ex2f_(c[2]*C2E), ex2f_(c[3]*C2E));
        float4 e1 = make_float4(ex2f_(c[4]*C2E), ex2f_(c[5]*C2E),
                                ex2f_(c[6]*C2E), ex2f_(c[7]*C2E));
        if (isq) {
            *(float4*)&g_eq[o0] = e0;
            *(float4*)&g_eq[o1] = e1;
        } else {
            *(float4*)&g_k[o0] = make_float4(c[0], c[1], c[2], c[3]);
            *(float4*)&g_k[o1] = make_float4(c[4], c[5], c[6], c[7]);
            *(float4*)&g_ek[o0] = e0;
            *(float4*)&g_ek[o1] = e1;
        }
    }
}

// ---------------------------------------------------------------------------
// Kernel 2: scores, factorized exp + pairwise rcp-combine + packed FMA.
//   s0/(1+a0) + s1/(1+a1) = [sab + s0*a1 + s1*a0] / [(1+a0)(1+a1)]
// -> 1 RCP per 2 u. Packed lanes = the two u-pairs of a u-quad; tiles stored
// u-swizzled (u0,u2,u1,u3) so one LDS.128 gives both f32x2 operand pairs.
// Block 32q x 32v, 128 thr; thread 2q x 4v x all u. score' = -2*sum (const
// Sum(scale) shift dropped; softmax shift-invariant, scores not an output).
// ---------------------------------------------------------------------------
__global__ __launch_bounds__(128) void scores_kernel(const float* __restrict__ scale)
{
    __shared__ __align__(16) float Qs[32][132];    // stride 132: 16B-aligned rows
    __shared__ __align__(16) float Ks[32][132];
    __shared__ __align__(8)  float2 Sa[32], Sb[32], Sab[32];

    int b  = blockIdx.z;
    int qt = blockIdx.y;
    int vt = blockIdx.x;
    int t  = threadIdx.x;

    const float* qg_ = g_eq + (size_t)(b * TQ + qt * 32) * UU;
    const float* kg_ = g_ek + (size_t)(b * TV + vt * 32) * UU;

    #pragma unroll
    for (int j = 0; j < 8; j++) {
        int i = t + j * 128;
        int r = i >> 5, c = (i & 31) << 2;
        float4 x = *(const float4*)&qg_[(size_t)r * UU + c];
        *(float4*)&Qs[r][c] = make_float4(x.x, x.z, x.y, x.w);   // u-swizzle
        float4 y = *(const float4*)&kg_[(size_t)r * UU + c];
        *(float4*)&Ks[r][c] = make_float4(y.x, y.z, y.y, y.w);
    }
    if (t < 32) {
        float4 s = *(const float4*)&scale[t * 4];
        Sa[t]  = make_float2(s.x, s.z);
        Sb[t]  = make_float2(s.y, s.w);
        Sab[t] = make_float2(s.x + s.y, s.z + s.w);
    }
    __syncthreads();

    int vg = t & 7;           // v rows vg*4..+3
    int qg = t >> 3;          // q rows qg*2..+1
    int v0 = vg * 4, q0 = qg * 2;

    ull acc[2][4];
    #pragma unroll
    for (int i = 0; i < 2; i++)
        #pragma unroll
        for (int j = 0; j < 4; j++) acc[i][j] = 0ULL;

    #pragma unroll 2
    for (int uq = 0; uq < 32; uq++) {
        ull sa  = *(const ull*)&Sa[uq];
        ull sb  = *(const ull*)&Sb[uq];
        ull sab = *(const ull*)&Sab[uq];
        ulonglong2 k4[4];
        #pragma unroll
        for (int v = 0; v < 4; v++)
            k4[v] = *(const ulonglong2*)&Ks[v0 + v][uq * 4];
        #pragma unroll
        for (int qi = 0; qi < 2; qi++) {
            ulonglong2 q4 = *(const ulonglong2*)&Qs[q0 + qi][uq * 4];
            #pragma unroll
            for (int v = 0; v < 4; v++) {
                ull A = mul2_(q4.x, k4[v].x);     // (a_u0, a_u2)
                ull B = mul2_(q4.y, k4[v].y);     // (a_u1, a_u3)
                ull U = add2_(A, ONE2);
                ull P = fma2_(U, B, U);           // (1+a)(1+b)
                ull N = fma2_(sb, A, sab);
                N = fma2_(sa, B, N);
                float pl, ph; upk2_(P, pl, ph);
                ull R = pk2_(rcpf_(pl), rcpf_(ph));
                acc[qi][v] = fma2_(N, R, acc[qi][v]);
            }
        }
    }

    #pragma unroll
    for (int qi = 0; qi < 2; qi++) {
        float* out = g_scores + (size_t)(b * TQ + qt * 32 + q0 + qi) * TV + vt * 32 + v0;
        #pragma unroll
        for (int v = 0; v < 4; v++) {
            float lo, hi; upk2_(acc[qi][v], lo, hi);
            out[v] = -2.0f * (lo + hi);
        }
    }
}

// ---------------------------------------------------------------------------
// Kernel 3: row softmax over Tv=2048. One block per (b,q) row.
// ---------------------------------------------------------------------------
__global__ __launch_bounds__(256) void softmax_kernel(float* __restrict__ wout)
{
    __shared__ float red[8];
    int row = blockIdx.x;
    int t   = threadIdx.x;

    const float4* in4 = (const float4*)(g_scores + (size_t)row * TV);
    float4 a = in4[t];
    float4 b = in4[t + 256];

    float m = fmaxf(fmaxf(fmaxf(a.x, a.y), fmaxf(a.z, a.w)),
                    fmaxf(fmaxf(b.x, b.y), fmaxf(b.z, b.w)));
    #pragma unroll
    for (int off = 16; off; off >>= 1)
        m = fmaxf(m, __shfl_xor_sync(0xffffffffu, m, off));
    if ((t & 31) == 0) red[t >> 5] = m;
    __syncthreads();
    m = red[0];
    #pragma unroll
    for (int i = 1; i < 8; i++) m = fmaxf(m, red[i]);

    const float L2E = 1.44269504088896341f;
    float e0 = ex2f_((a.x - m) * L2E), e1 = ex2f_((a.y - m) * L2E);
    float e2 = ex2f_((a.z - m) * L2E), e3 = ex2f_((a.w - m) * L2E);
    float e4 = ex2f_((b.x - m) * L2E), e5 = ex2f_((b.y - m) * L2E);
    float e6 = ex2f_((b.z - m) * L2E), e7 = ex2f_((b.w - m) * L2E);
    float s = ((e0 + e1) + (e2 + e3)) + ((e4 + e5) + (e6 + e7));
    #pragma unroll
    for (int off = 16; off; off >>= 1)
        s += __shfl_xor_sync(0xffffffffu, s, off);
    __syncthreads();
    if ((t & 31) == 0) red[t >> 5] = s;
    __syncthreads();
    float tot = 0.0f;
    #pragma unroll
    for (int i = 0; i < 8; i++) tot += red[i];
    float inv = rcpf_(tot);

    float4* o4 = (float4*)(wout + (size_t)row * TV);
    o4[t]       = make_float4(e0 * inv, e1 * inv, e2 * inv, e3 * inv);
    o4[t + 256] = make_float4(e4 * inv, e5 * inv, e6 * inv, e7 * inv);
}

// ---------------------------------------------------------------------------
// Kernel 4: context partials, packed over u-pairs.
// ctx[b,q,u] = sum_v w[b,q,v]*k[b,v,u]. Grid (8 v-chunks of 256, 32 row-tiles
// of 32 q). 256 thr: ug = t&31 (4 u = 2 packed), qg = t>>5 (4 q rows).
// ---------------------------------------------------------------------------
__global__ __launch_bounds__(256) void ctx_partial(const float* __restrict__ wts)
{
    __shared__ __align__(16) float Ks2[64][128];   // [v][u]
    __shared__ float Wst[64][33];                  // [v][q], stride 33

    int chunk = blockIdx.x;          // 0..7 -> v in [chunk*256, +256)
    int rt    = blockIdx.y;          // 0..31
    int r0    = rt * 32;             // global row base (b*256+q)
    int bbb   = r0 >> 8;             // batch
    int t     = threadIdx.x;
    int ug    = t & 31;              // u = ug*4..+3
    int qg    = t >> 5;              // q rows qg*4..+3

    ull acc[4][2];
    #pragma unroll
    for (int q = 0; q < 4; q++) { acc[q][0] = 0ULL; acc[q][1] = 0ULL; }

    #pragma unroll 1
    for (int vt = 0; vt < 4; vt++) {
        int vbase = chunk * 256 + vt * 64;
        #pragma unroll
        for (int j = 0; j < 8; j++) {
            int i = t + j * 256;
            int v = i >> 5, c = (i & 31) << 2;
            *(float4*)&Ks2[v][c] =
                *(const float4*)&g_k[(size_t)(bbb * TV + vbase + v) * UU + c];
        }
        #pragma unroll
        for (int j = 0; j < 8; j++) {
            int i = t + j * 256;
            int q = i >> 6, v = i & 63;
            Wst[v][q] = wts[(size_t)(r0 + q) * TV + vbase + v];
        }
        __syncthreads();

        #pragma unroll 8
        for (int v = 0; v < 64; v++) {
            ulonglong2 kk = *(const ulonglong2*)&Ks2[v][ug * 4];
            #pragma unroll
            for (int q = 0; q < 4; q++) {
                float w = Wst[v][qg * 4 + q];
                ull w2 = pk2_(w, w);
                acc[q][0] = fma2_(w2, kk.x, acc[q][0]);
                acc[q][1] = fma2_(w2, kk.y, acc[q][1]);
            }
        }
        __syncthreads();
    }

    #pragma unroll
    for (int q = 0; q < 4; q++) {
        float c0, c1, c2, c3;
        upk2_(acc[q][0], c0, c1);
        upk2_(acc[q][1], c2, c3);
        *(float4*)&g_part[chunk][(size_t)(r0 + qg * 4 + q) * UU + ug * 4] =
            make_float4(c0, c1, c2, c3);
    }
}

// ---------------------------------------------------------------------------
// Kernel 5: reduce 8 partials -> context into d_out[0 .. CTX_SIZE)
// ---------------------------------------------------------------------------
__global__ __launch_bounds__(256) void ctx_reduce(float* __restrict__ out)
{
    int i = blockIdx.x * 256 + threadIdx.x;   // float4 index, 32768 total
    float4 s = ((const float4*)g_part[0])[i];
    #pragma unroll
    for (int c = 1; c < NCHUNK; c++) {
        float4 p = ((const float4*)g_part[c])[i];
        s.x += p.x; s.y += p.y; s.z += p.z; s.w += p.w;
    }
    ((float4*)out)[i] = s;
}

extern "C" void kernel_launch(void* const* d_in, const int* in_sizes, int n_in,
                              void* d_out, int out_size)
{
    (void)in_sizes; (void)n_in; (void)out_size;
    const float* dq    = (const float*)d_in[0];   // [4,256,512]
    const float* ev    = (const float*)d_in[1];   // [4,2048,512]
    const float* W1    = (const float*)d_in[2];   // [512,128]
    const float* W2    = (const float*)d_in[3];   // [512,128]
    const float* scale = (const float*)d_in[4];   // [128]
    float* out  = (float*)d_out;                  // context [131072] ++ weights [2097152]
    float* wout = out + CTX_SIZE;

    proj_gemm<<<144, 256>>>(dq, ev, W1, W2);
    scores_kernel<<<dim3(TV / 32, TQ / 32, BB), 128>>>(scale);
    softmax_kernel<<<NROWS_Q, 256>>>(wout);
    ctx_partial<<<dim3(NCHUNK, 32), 256>>>(wout);
    ctx_reduce<<<CTX_SIZE / 4 / 256, 256>>>(out);
}

// round 9
// speedup vs baseline: 1.5341x; 1.0372x over previous
#include <cuda_runtime.h>

#define BB   4
#define TQ   256
#define TV   2048
#define DD   512
#define UU   128
#define NROWS_Q (BB*TQ)          // 1024
#define NROWS_K (BB*TV)          // 8192
#define CTX_SIZE (NROWS_Q*UU)    // 131072
#define NCHUNK 16

typedef unsigned long long ull;

// Scratch (no cudaMalloc allowed)
__device__ float g_eq[NROWS_Q*UU];          // e^{2q}  0.5 MB
__device__ float g_k [NROWS_K*UU];          // raw k   4 MB
__device__ float g_ek[NROWS_K*UU];          // e^{2k}  4 MB
__device__ float g_scores[NROWS_Q*TV];      // 8 MB
__device__ float g_part[NCHUNK][CTX_SIZE];  // 8 MB

__device__ __forceinline__ float ex2f_(float x){ float y; asm("ex2.approx.f32 %0, %1;" : "=f"(y) : "f"(x)); return y; }
__device__ __forceinline__ float rcpf_(float x){ float y; asm("rcp.approx.f32 %0, %1;" : "=f"(y) : "f"(x)); return y; }

// Packed f32x2 (Blackwell): 2x fp32 FMA throughput, only reachable via PTX.
__device__ __forceinline__ ull pk2_(float lo, float hi){ ull r; asm("mov.b64 %0, {%1, %2};" : "=l"(r) : "f"(lo), "f"(hi)); return r; }
__device__ __forceinline__ void upk2_(ull v, float& lo, float& hi){ asm("mov.b64 {%0, %1}, %2;" : "=f"(lo), "=f"(hi) : "l"(v)); }
__device__ __forceinline__ ull fma2_(ull a, ull b, ull c){ ull d; asm("fma.rn.f32x2 %0, %1, %2, %3;" : "=l"(d) : "l"(a), "l"(b), "l"(c)); return d; }
__device__ __forceinline__ ull mul2_(ull a, ull b){ ull d; asm("mul.rn.f32x2 %0, %1, %2;" : "=l"(d) : "l"(a), "l"(b)); return d; }
__device__ __forceinline__ ull add2_(ull a, ull b){ ull d; asm("add.rn.f32x2 %0, %1, %2;" : "=l"(d) : "l"(a), "l"(b)); return d; }
#define ONE2 0x3F8000003F800000ULL

#define C2E 2.88539008177792681f   /* 2*log2(e) */

// ---------------------------------------------------------------------------
// Kernel 1: projections + exp epilogue, packed-FMA mainloop.
// C[M,128] = A[M,512] @ W[512,128] fp32. bid<16 -> q (store e^{2q} only),
// else -> k (store raw k AND e^{2k}). BM=64, BN=128, BK=16, thread 4m x (4 n-pairs).
// ---------------------------------------------------------------------------
__global__ __launch_bounds__(256) void proj_gemm(
    const float* __restrict__ dq, const float* __restrict__ ev,
    const float* __restrict__ W1, const float* __restrict__ W2)
{
    __shared__ __align__(16) float As[16][68];    // [kk][m], padded
    __shared__ __align__(16) float Bs[16][128];   // [kk][n]

    int bid = blockIdx.x;
    bool isq = (bid < 16);
    const float* A; const float* W; int mbase;
    if (isq) { A = dq; W = W1; mbase = bid * 64; }
    else     { A = ev; W = W2; mbase = (bid - 16) * 64; }

    int t  = threadIdx.x;
    int ty = t >> 4;          // 0..15 (row group)
    int tx = t & 15;          // 0..15 (col group)
    int lr = t >> 2;          // 0..63 (A load row)
    int lc = (t & 3) << 2;    // 0,4,8,12 (A load col quad)

    ull acc[4][4];
    #pragma unroll
    for (int i = 0; i < 4; i++)
        #pragma unroll
        for (int j = 0; j < 4; j++) acc[i][j] = 0ULL;

    for (int k0 = 0; k0 < DD; k0 += 16) {
        float4 av = *(const float4*)&A[(size_t)(mbase + lr) * DD + k0 + lc];
        As[lc + 0][lr] = av.x; As[lc + 1][lr] = av.y;
        As[lc + 2][lr] = av.z; As[lc + 3][lr] = av.w;
        {
            int i0 = t, i1 = t + 256;
            *(float4*)&Bs[i0 >> 5][(i0 & 31) << 2] =
                *(const float4*)&W[(size_t)(k0 + (i0 >> 5)) * UU + ((i0 & 31) << 2)];
            *(float4*)&Bs[i1 >> 5][(i1 & 31) << 2] =
                *(const float4*)&W[(size_t)(k0 + (i1 >> 5)) * UU + ((i1 & 31) << 2)];
        }
        __syncthreads();

        #pragma unroll
        for (int kk = 0; kk < 16; kk++) {
            float4 a4 = *(const float4*)&As[kk][ty * 4];
            ulonglong2 b0 = *(const ulonglong2*)&Bs[kk][tx * 4];
            ulonglong2 b1 = *(const ulonglong2*)&Bs[kk][64 + tx * 4];
            float a[4] = {a4.x, a4.y, a4.z, a4.w};
            #pragma unroll
            for (int i = 0; i < 4; i++) {
                ull ad = pk2_(a[i], a[i]);
                acc[i][0] = fma2_(ad, b0.x, acc[i][0]);
                acc[i][1] = fma2_(ad, b0.y, acc[i][1]);
                acc[i][2] = fma2_(ad, b1.x, acc[i][2]);
                acc[i][3] = fma2_(ad, b1.y, acc[i][3]);
            }
        }
        __syncthreads();
    }

    #pragma unroll
    for (int i = 0; i < 4; i++) {
        float c[8];
        upk2_(acc[i][0], c[0], c[1]); upk2_(acc[i][1], c[2], c[3]);
        upk2_(acc[i][2], c[4], c[5]); upk2_(acc[i][3], c[6], c[7]);
        int row = mbase + ty * 4 + i;
        size_t o0 = (size_t)row * UU + tx * 4;
        size_t o1 = o0 + 64;
        float4 e0 = make_float4(ex2f_(c[0]*C2E), ex2f_(c[1]*C2E),
                                ex2f_(c[2]*C2E), ex2f_(c[3]*C2E));
        float4 e1 = make_float4(ex2f_(c[4]*C2E), ex2f_(c[5]*C2E),
                                ex2f_(c[6]*C2E), ex2f_(c[7]*C2E));
        if (isq) {
            *(float4*)&g_eq[o0] = e0;
            *(float4*)&g_eq[o1] = e1;
        } else {
            *(float4*)&g_k[o0] = make_float4(c[0], c[1], c[2], c[3]);
            *(float4*)&g_k[o1] = make_float4(c[4], c[5], c[6], c[7]);
            *(float4*)&g_ek[o0] = e0;
            *(float4*)&g_ek[o1] = e1;
        }
    }
}

// ---------------------------------------------------------------------------
// Kernel 2: scores, factorized exp + pairwise rcp-combine + packed FMA.
//   s0/(1+a0) + s1/(1+a1) = [sab + s0*a1 + s1*a0] / [(1+a0)(1+a1)]
// -> 1 RCP per 2 u. Packed lanes = the two u-pairs of a u-quad; tiles stored
// u-swizzled (u0,u2,u1,u3) so one LDS.128 gives both f32x2 operand pairs.
// Block 32q x 32v, 128 thr; thread 2q x 4v x all u. score' = -2*sum (const
// Sum(scale) shift dropped; softmax shift-invariant, scores not an output).
// ---------------------------------------------------------------------------
__global__ __launch_bounds__(128) void scores_kernel(const float* __restrict__ scale)
{
    __shared__ __align__(16) float Qs[32][132];    // stride 132: 16B-aligned rows
    __shared__ __align__(16) float Ks[32][132];
    __shared__ __align__(8)  float2 Sa[32], Sb[32], Sab[32];

    int b  = blockIdx.z;
    int qt = blockIdx.y;
    int vt = blockIdx.x;
    int t  = threadIdx.x;

    const float* qg_ = g_eq + (size_t)(b * TQ + qt * 32) * UU;
    const float* kg_ = g_ek + (size_t)(b * TV + vt * 32) * UU;

    #pragma unroll
    for (int j = 0; j < 8; j++) {
        int i = t + j * 128;
        int r = i >> 5, c = (i & 31) << 2;
        float4 x = *(const float4*)&qg_[(size_t)r * UU + c];
        *(float4*)&Qs[r][c] = make_float4(x.x, x.z, x.y, x.w);   // u-swizzle
        float4 y = *(const float4*)&kg_[(size_t)r * UU + c];
        *(float4*)&Ks[r][c] = make_float4(y.x, y.z, y.y, y.w);
    }
    if (t < 32) {
        float4 s = *(const float4*)&scale[t * 4];
        Sa[t]  = make_float2(s.x, s.z);
        Sb[t]  = make_float2(s.y, s.w);
        Sab[t] = make_float2(s.x + s.y, s.z + s.w);
    }
    __syncthreads();

    int vg = t & 7;           // v rows vg*4..+3
    int qg = t >> 3;          // q rows qg*2..+1
    int v0 = vg * 4, q0 = qg * 2;

    ull acc[2][4];
    #pragma unroll
    for (int i = 0; i < 2; i++)
        #pragma unroll
        for (int j = 0; j < 4; j++) acc[i][j] = 0ULL;

    #pragma unroll 2
    for (int uq = 0; uq < 32; uq++) {
        ull sa  = *(const ull*)&Sa[uq];
        ull sb  = *(const ull*)&Sb[uq];
        ull sab = *(const ull*)&Sab[uq];
        ulonglong2 k4[4];
        #pragma unroll
        for (int v = 0; v < 4; v++)
            k4[v] = *(const ulonglong2*)&Ks[v0 + v][uq * 4];
        #pragma unroll
        for (int qi = 0; qi < 2; qi++) {
            ulonglong2 q4 = *(const ulonglong2*)&Qs[q0 + qi][uq * 4];
            #pragma unroll
            for (int v = 0; v < 4; v++) {
                ull A = mul2_(q4.x, k4[v].x);     // (a_u0, a_u2)
                ull B = mul2_(q4.y, k4[v].y);     // (a_u1, a_u3)
                ull U = add2_(A, ONE2);
                ull P = fma2_(U, B, U);           // (1+a)(1+b)
                ull N = fma2_(sb, A, sab);
                N = fma2_(sa, B, N);
                float pl, ph; upk2_(P, pl, ph);
                ull R = pk2_(rcpf_(pl), rcpf_(ph));
                acc[qi][v] = fma2_(N, R, acc[qi][v]);
            }
        }
    }

    #pragma unroll
    for (int qi = 0; qi < 2; qi++) {
        float* out = g_scores + (size_t)(b * TQ + qt * 32 + q0 + qi) * TV + vt * 32 + v0;
        #pragma unroll
        for (int v = 0; v < 4; v++) {
            float lo, hi; upk2_(acc[qi][v], lo, hi);
            out[v] = -2.0f * (lo + hi);
        }
    }
}

// ---------------------------------------------------------------------------
// Kernel 3: row softmax over Tv=2048. One block per (b,q) row.
// ---------------------------------------------------------------------------
__global__ __launch_bounds__(256) void softmax_kernel(float* __restrict__ wout)
{
    __shared__ float red[8];
    int row = blockIdx.x;
    int t   = threadIdx.x;

    const float4* in4 = (const float4*)(g_scores + (size_t)row * TV);
    float4 a = in4[t];
    float4 b = in4[t + 256];

    float m = fmaxf(fmaxf(fmaxf(a.x, a.y), fmaxf(a.z, a.w)),
                    fmaxf(fmaxf(b.x, b.y), fmaxf(b.z, b.w)));
    #pragma unroll
    for (int off = 16; off; off >>= 1)
        m = fmaxf(m, __shfl_xor_sync(0xffffffffu, m, off));
    if ((t & 31) == 0) red[t >> 5] = m;
    __syncthreads();
    m = red[0];
    #pragma unroll
    for (int i = 1; i < 8; i++) m = fmaxf(m, red[i]);

    const float L2E = 1.44269504088896341f;
    float e0 = ex2f_((a.x - m) * L2E), e1 = ex2f_((a.y - m) * L2E);
    float e2 = ex2f_((a.z - m) * L2E), e3 = ex2f_((a.w - m) * L2E);
    float e4 = ex2f_((b.x - m) * L2E), e5 = ex2f_((b.y - m) * L2E);
    float e6 = ex2f_((b.z - m) * L2E), e7 = ex2f_((b.w - m) * L2E);
    float s = ((e0 + e1) + (e2 + e3)) + ((e4 + e5) + (e6 + e7));
    #pragma unroll
    for (int off = 16; off; off >>= 1)
        s += __shfl_xor_sync(0xffffffffu, s, off);
    __syncthreads();
    if ((t & 31) == 0) red[t >> 5] = s;
    __syncthreads();
    float tot = 0.0f;
    #pragma unroll
    for (int i = 0; i < 8; i++) tot += red[i];
    float inv = rcpf_(tot);

    float4* o4 = (float4*)(wout + (size_t)row * TV);
    o4[t]       = make_float4(e0 * inv, e1 * inv, e2 * inv, e3 * inv);
    o4[t + 256] = make_float4(e4 * inv, e5 * inv, e6 * inv, e7 * inv);
}

// ---------------------------------------------------------------------------
// Kernel 4: context partials, packed over q-pairs, w pre-packed in smem.
// ctx[b,q,u] = sum_v w[b,q,v]*k[b,v,u].
// Grid (16 v-chunks of 128, 32 q-tiles of 32). Block 128 thr:
// ug = t&31 (u-quad), qg = t>>5 (8 q rows = 4 q-pairs). 16 packed accs.
// Inner per v: 1 LDS.128 (k) + 2 broadcast LDS.128 (w-pairs) + 16 fma2.
// ---------------------------------------------------------------------------
__global__ __launch_bounds__(128) void ctx_partial(const float* __restrict__ wts)
{
    __shared__ __align__(16) float Ks2[64][128];   // [v][u]
    __shared__ __align__(16) ull   Wp[64][18];     // [v][qpair] (w_q, w_q+1); stride 18 -> 16B-aligned rows

    int chunk = blockIdx.x;          // 0..15 -> v in [chunk*128, +128)
    int rt    = blockIdx.y;          // 0..31 -> q rows rt*32..+31
    int r0    = rt * 32;             // global row base (b*256+q)
    int bbb   = r0 >> 8;             // batch
    int t     = threadIdx.x;
    int ug    = t & 31;              // u = ug*4..+3
    int qg    = t >> 5;              // q-pairs qg*4..+3  (q rows qg*8..+7)

    ull acc[4][4];                   // [u][qpair]
    #pragma unroll
    for (int u = 0; u < 4; u++)
        #pragma unroll
        for (int p = 0; p < 4; p++) acc[u][p] = 0ULL;

    #pragma unroll 1
    for (int vt = 0; vt < 2; vt++) {
        int vbase = chunk * 128 + vt * 64;
        #pragma unroll
        for (int j = 0; j < 16; j++) {
            int i = t + j * 128;
            int v = i >> 5, c = (i & 31) << 2;
            *(float4*)&Ks2[v][c] =
                *(const float4*)&g_k[(size_t)(bbb * TV + vbase + v) * UU + c];
        }
        #pragma unroll
        for (int j = 0; j < 8; j++) {
            int i = t + j * 128;
            int qp = i >> 6, v = i & 63;          // qp 0..15, v 0..63
            const float* wp = &wts[(size_t)(r0 + qp * 2) * TV + vbase + v];
            Wp[v][qp] = pk2_(wp[0], wp[TV]);
        }
        __syncthreads();

        #pragma unroll 4
        for (int v = 0; v < 64; v++) {
            float4 kf = *(const float4*)&Ks2[v][ug * 4];
            ull k0 = pk2_(kf.x, kf.x), k1 = pk2_(kf.y, kf.y);
            ull k2 = pk2_(kf.z, kf.z), k3 = pk2_(kf.w, kf.w);
            ulonglong2 wa = *(const ulonglong2*)&Wp[v][qg * 4];
            ulonglong2 wb = *(const ulonglong2*)&Wp[v][qg * 4 + 2];
            acc[0][0] = fma2_(k0, wa.x, acc[0][0]);
            acc[1][0] = fma2_(k1, wa.x, acc[1][0]);
            acc[2][0] = fma2_(k2, wa.x, acc[2][0]);
            acc[3][0] = fma2_(k3, wa.x, acc[3][0]);
            acc[0][1] = fma2_(k0, wa.y, acc[0][1]);
            acc[1][1] = fma2_(k1, wa.y, acc[1][1]);
            acc[2][1] = fma2_(k2, wa.y, acc[2][1]);
            acc[3][1] = fma2_(k3, wa.y, acc[3][1]);
            acc[0][2] = fma2_(k0, wb.x, acc[0][2]);
            acc[1][2] = fma2_(k1, wb.x, acc[1][2]);
            acc[2][2] = fma2_(k2, wb.x, acc[2][2]);
            acc[3][2] = fma2_(k3, wb.x, acc[3][2]);
            acc[0][3] = fma2_(k0, wb.y, acc[0][3]);
            acc[1][3] = fma2_(k1, wb.y, acc[1][3]);
            acc[2][3] = fma2_(k2, wb.y, acc[2][3]);
            acc[3][3] = fma2_(k3, wb.y, acc[3][3]);
        }
        __syncthreads();
    }

    #pragma unroll
    for (int p = 0; p < 4; p++) {
        float lo[4], hi[4];
        upk2_(acc[0][p], lo[0], hi[0]);
        upk2_(acc[1][p], lo[1], hi[1]);
        upk2_(acc[2][p], lo[2], hi[2]);
        upk2_(acc[3][p], lo[3], hi[3]);
        int q0 = r0 + qg * 8 + p * 2;
        *(float4*)&g_part[chunk][(size_t)q0 * UU + ug * 4] =
            make_float4(lo[0], lo[1], lo[2], lo[3]);
        *(float4*)&g_part[chunk][(size_t)(q0 + 1) * UU + ug * 4] =
            make_float4(hi[0], hi[1], hi[2], hi[3]);
    }
}

// ---------------------------------------------------------------------------
// Kernel 5: reduce 16 partials -> context into d_out[0 .. CTX_SIZE)
// ---------------------------------------------------------------------------
__global__ __launch_bounds__(256) void ctx_reduce(float* __restrict__ out)
{
    int i = blockIdx.x * 256 + threadIdx.x;   // float4 index, 32768 total
    float4 s = ((const float4*)g_part[0])[i];
    #pragma unroll
    for (int c = 1; c < NCHUNK; c++) {
        float4 p = ((const float4*)g_part[c])[i];
        s.x += p.x; s.y += p.y; s.z += p.z; s.w += p.w;
    }
    ((float4*)out)[i] = s;
}

extern "C" void kernel_launch(void* const* d_in, const int* in_sizes, int n_in,
                              void* d_out, int out_size)
{
    (void)in_sizes; (void)n_in; (void)out_size;
    const float* dq    = (const float*)d_in[0];   // [4,256,512]
    const float* ev    = (const float*)d_in[1];   // [4,2048,512]
    const float* W1    = (const float*)d_in[2];   // [512,128]
    const float* W2    = (const float*)d_in[3];   // [512,128]
    const float* scale = (const float*)d_in[4];   // [128]
    float* out  = (float*)d_out;                  // context [131072] ++ weights [2097152]
    float* wout = out + CTX_SIZE;

    proj_gemm<<<144, 256>>>(dq, ev, W1, W2);
    scores_kernel<<<dim3(TV / 32, TQ / 32, BB), 128>>>(scale);
    softmax_kernel<<<NROWS_Q, 256>>>(wout);
    ctx_partial<<<dim3(NCHUNK, 32), 128>>>(wout);
    ctx_reduce<<<CTX_SIZE / 4 / 256, 256>>>(out);
}